// round 3
// baseline (speedup 1.0000x reference)
#include <cuda_runtime.h>
#include <cuda_bf16.h>

// Stacked-LSTM wavefront solver, round 3 (R2 design + alignment fix: As pad 17 -> 18).
// Cells (t,l) on anti-diagonal d = t+l are independent; persistent kernel sweeps
// d = 0..126 with a software grid barrier. Per diagonal each CTA-job computes a
// 16x512 @ 512x(4x32) GEMM slice (all 4 gates for 32 h-cols of one cell) fused
// with the LSTM elementwise update. Gate-interleaved weights pre-rearranged into
// g_Wr so the inner loop is LDS.64(broadcast) + LDS.128 + 8 FFMA.

#define NBLK 296   // 2 CTAs/SM, all co-resident -> spin barrier safe
#define NTHR 256
#define KT   64    // K-tile
#define APAD 18    // even -> float2 loads 8B-aligned; conflict-free stores

__device__ float g_c[64][16][256];
__device__ float g_h[2][64][16][256];    // h double-buffered by t-parity
__device__ float g_Wr[512][1024];        // W rearranged: [k][sl*128 + j*4 + gate]
__device__ unsigned g_count = 0;
__device__ unsigned g_phase = 0;

__device__ __forceinline__ float sigf(float v) { return 1.0f / (1.0f + __expf(-v)); }
__device__ __forceinline__ float tanhfast(float v) {
  float e = __expf(2.0f * v);          // inf-safe: large v -> 1, large -v -> -1
  return 1.0f - 2.0f / (e + 1.0f);
}

__device__ __forceinline__ void grid_barrier(unsigned target) {
  __syncthreads();
  if (threadIdx.x == 0) {
    __threadfence();
    if (atomicAdd(&g_count, 1) == (unsigned)(NBLK - 1)) {
      atomicExch(&g_count, 0);
      __threadfence();
      atomicAdd(&g_phase, 1);
    } else {
      while (*((volatile unsigned*)&g_phase) != target) { __nanosleep(40); }
    }
    __threadfence();
  }
  __syncthreads();
}

__global__ __launch_bounds__(NTHR, 2) void lstm_wave(
    const float* __restrict__ x,      // (16, 64, 256)
    const float* __restrict__ ist,    // (64, 2, 16, 256)
    const float* __restrict__ W,      // (512, 1024)
    const float* __restrict__ bias,   // (1024,)
    float* __restrict__ out)          // (16, 64, 256)
{
  __shared__ __align__(16) float Bs[KT][128];    // gate-interleaved W tile
  __shared__ __align__(16) float As[KT][APAD];   // A^T tile
  __shared__ unsigned s_base;

  const int tid = threadIdx.x;
  if (tid == 0) s_base = *((volatile unsigned*)&g_phase);  // phase persists across replays
  __syncthreads();
  const unsigned base = s_base;

  // ---- init: c, h(parity 1) from init_state; rearrange W into g_Wr ----
  const int total = 64 * 16 * 256;
  for (int e = blockIdx.x * NTHR + tid; e < total; e += NBLK * NTHR) {
    int l = e >> 12, rm = e & 4095;
    __stcg(&((float*)g_c)[e],         ist[(l * 2 + 0) * 4096 + rm]);
    __stcg(&((float*)g_h)[total + e], ist[(l * 2 + 1) * 4096 + rm]);
  }
  // g_Wr[k][sl*128 + j*4 + g] = W[k][g*256 + sl*32 + j]
  for (int e = blockIdx.x * NTHR + tid; e < 512 * 1024; e += NBLK * NTHR) {
    int k = e >> 10, c = e & 1023;
    int sl = c >> 7, r = c & 127, j = r >> 2, g = r & 3;
    __stcg(&g_Wr[k][c], W[k * 1024 + g * 256 + sl * 32 + j]);
  }
  grid_barrier(base + 1);

  // ---- wavefront over anti-diagonals ----
  for (int d = 0; d < 127; ++d) {
    const int lo = (d > 63) ? d - 63 : 0;
    const int hi = (d < 63) ? d : 63;
    const int ncells = hi - lo + 1;
    const int njobs = ncells * 8;                 // 8 slices of 32 cols per cell

    for (int job = blockIdx.x; job < njobs; job += NBLK) {
      const int ci = job % ncells;
      const int sl = job / ncells;
      const int l = lo + ci, t = d - l;
      const int m0 = sl * 32;
      const int pin = t & 1;                      // parity of h(t)
      const int prec = pin ^ 1;                   // parity of h(t-1) / init slot

      float acc[8];                               // [gate*2 + row_in_pair]
      #pragma unroll
      for (int i = 0; i < 8; ++i) acc[i] = 0.0f;
      const int j = tid & 31;                     // col within slice
      const int rg = tid >> 5;                    // row pair (2 rows each)

      for (int kt0 = 0; kt0 < 512; kt0 += KT) {
        // W tile: straight float4 copy from rearranged layout (conflict-free)
        #pragma unroll
        for (int e4 = tid; e4 < KT * 32; e4 += NTHR) {
          int k = e4 >> 5, c4 = (e4 & 31) * 4;
          *(float4*)&Bs[k][c4] = *(const float4*)&g_Wr[kt0 + k][m0 * 4 + c4];
        }
        // A tile (transposed): As[k][r] = [inp | h_prev][r][kt0+k]
        #pragma unroll
        for (int e = tid; e < KT * 16; e += NTHR) {
          int r = e >> 6, k = e & 63;             // k-contiguous -> coalesced
          int kg = kt0 + k;
          float v;
          if (kg < 256) {
            v = (l == 0) ? x[(r * 64 + t) * 256 + kg]
                         : __ldcg(&g_h[pin][l - 1][r][kg]);
          } else {
            v = __ldcg(&g_h[prec][l][r][kg - 256]);
          }
          As[k][r] = v;
        }
        __syncthreads();
        #pragma unroll 8
        for (int k = 0; k < KT; ++k) {
          float2 a = *(const float2*)&As[k][rg * 2];   // warp-uniform broadcast
          float4 w = *(const float4*)&Bs[k][j * 4];
          acc[0] += a.x * w.x; acc[1] += a.y * w.x;   // gate i
          acc[2] += a.x * w.y; acc[3] += a.y * w.y;   // gate j
          acc[4] += a.x * w.z; acc[5] += a.y * w.z;   // gate f
          acc[6] += a.x * w.w; acc[7] += a.y * w.w;   // gate o
        }
        __syncthreads();
      }

      // fused LSTM cell elementwise (2 rows x 1 col per thread)
      const int m = m0 + j;
      const float bi = bias[m], bjv = bias[256 + m], bf = bias[512 + m], bo = bias[768 + m];
      #pragma unroll
      for (int rr = 0; rr < 2; ++rr) {
        const int r = rg * 2 + rr;
        float zi = acc[0 + rr] + bi;
        float zj = acc[2 + rr] + bjv;
        float zf = acc[4 + rr] + bf;
        float zo = acc[6 + rr] + bo;
        float lc = __ldcg(&g_c[l][r][m]);
        float nc = sigf(zf + 1.0f) * lc + sigf(zi) * tanhfast(zj);
        float nh = sigf(zo) * tanhfast(nc);
        __stcg(&g_c[l][r][m], nc);
        __stcg(&g_h[pin][l][r][m], nh);
        if (l == 63) out[(r * 64 + t) * 256 + m] = nh;
      }
    }
    grid_barrier(base + 2 + d);
  }
}

extern "C" void kernel_launch(void* const* d_in, const int* in_sizes, int n_in,
                              void* d_out, int out_size) {
  const float* x    = (const float*)d_in[0];
  const float* ist  = (const float*)d_in[1];
  const float* W    = (const float*)d_in[2];
  const float* bias = (const float*)d_in[3];
  float* out        = (float*)d_out;
  (void)in_sizes; (void)n_in; (void)out_size;
  lstm_wave<<<NBLK, NTHR>>>(x, ist, W, bias, out);
}

// round 5
// speedup vs baseline: 1.1175x; 1.1175x over previous
#include <cuda_runtime.h>
#include <cuda_bf16.h>
#include <cstdint>

// Stacked-LSTM wavefront, warp-level mma.sync edition (base sm_103 target:
// tcgen05 is unavailable because the harness compiles through compute_103 PTX).
// 128 persistent CTAs. CTA = (Mb, Ns): cells Mb*8..Mb*8+7, gate-blocked N-slice
// Ns (cols n = gate*16 + hc, hc = Ns*16..+15). Warp w owns cell Mb*8+w:
// computes m16 x n64 with K=512 in 8 chunks of 64, split-bf16 x3
// (Ah*Wh + Al*Wh + Ah*Wl) via mma.sync.m16n8k16. W hi/lo resident in SMEM
// (144B-padded rows -> conflict-free ldmatrix). No __syncthreads in mainloop;
// warps are fully independent between grid barriers.

#define NBLK 128
#define NTHR 256
#define WS_OFF 0                 // [2][512][72] bf16 = 147456 B
#define AS_OFF 147456            // [8][2][16][72] bf16 = 36864 B
#define DYN_BYTES 184320

__device__ float g_c[64][16][256];
__device__ float g_h[2][64][16][256];     // parity by t
__device__ unsigned g_count = 0;
__device__ unsigned g_phase = 0;

__device__ __forceinline__ uint32_t smem_u32(const void* p) {
  uint32_t a;
  asm("{ .reg .u64 t; cvta.to.shared.u64 t, %1; cvt.u32.u64 %0, t; }" : "=r"(a) : "l"(p));
  return a;
}
__device__ __forceinline__ void ldsm4(uint32_t* r, uint32_t a) {
  asm volatile("ldmatrix.sync.aligned.m8n8.x4.shared.b16 {%0,%1,%2,%3}, [%4];"
    : "=r"(r[0]), "=r"(r[1]), "=r"(r[2]), "=r"(r[3]) : "r"(a));
}
__device__ __forceinline__ void ldsm4t(uint32_t* r, uint32_t a) {
  asm volatile("ldmatrix.sync.aligned.m8n8.x4.trans.shared.b16 {%0,%1,%2,%3}, [%4];"
    : "=r"(r[0]), "=r"(r[1]), "=r"(r[2]), "=r"(r[3]) : "r"(a));
}
__device__ __forceinline__ void mma16816(float* c, const uint32_t* a, uint32_t b0, uint32_t b1) {
  asm volatile("mma.sync.aligned.m16n8k16.row.col.f32.bf16.bf16.f32 "
    "{%0,%1,%2,%3}, {%4,%5,%6,%7}, {%8,%9}, {%0,%1,%2,%3};"
    : "+f"(c[0]), "+f"(c[1]), "+f"(c[2]), "+f"(c[3])
    : "r"(a[0]), "r"(a[1]), "r"(a[2]), "r"(a[3]), "r"(b0), "r"(b1));
}

__device__ __forceinline__ float sigf(float v) { return 1.0f / (1.0f + __expf(-v)); }
__device__ __forceinline__ float tanhfast(float v) {
  float e = __expf(2.0f * v);
  return 1.0f - 2.0f / (e + 1.0f);
}

__device__ __forceinline__ void grid_barrier(unsigned target) {
  __syncthreads();
  if (threadIdx.x == 0) {
    __threadfence();
    if (atomicAdd(&g_count, 1) == (unsigned)(NBLK - 1)) {
      atomicExch(&g_count, 0);
      __threadfence();
      atomicAdd(&g_phase, 1);
    } else {
      while (*((volatile unsigned*)&g_phase) != target) { __nanosleep(40); }
    }
    __threadfence();
  }
  __syncthreads();
}

__global__ __launch_bounds__(NTHR, 1) void lstm_mma(
    const float* __restrict__ x,      // (16, 64, 256)
    const float* __restrict__ ist,    // (64, 2, 16, 256)
    const float* __restrict__ W,      // (512, 1024)
    const float* __restrict__ bias,   // (1024,)
    float* __restrict__ out)          // (16, 64, 256)
{
  extern __shared__ __align__(16) char dsm[];
  __shared__ unsigned s_base;

  const int tid = threadIdx.x;
  const int wid = tid >> 5;
  const int lane = tid & 31;
  const int bid = blockIdx.x;
  const int Ns = bid & 15;
  const int Mb = bid >> 4;
  const uint32_t sb = smem_u32(dsm);

  if (tid == 0) s_base = *((volatile unsigned*)&g_phase);
  __syncthreads();
  const unsigned pbase = s_base;

  // ---- W hi/lo into resident SMEM: WS[split][k][c], c = gate*16 + hc ----
  for (int e = tid; e < 512 * 64; e += NTHR) {
    const int k = e >> 6, c = e & 63;
    const int g = c >> 4, hc = c & 15;
    const float w = W[k * 1024 + g * 256 + Ns * 16 + hc];
    const __nv_bfloat16 hi = __float2bfloat16_rn(w);
    const __nv_bfloat16 lo = __float2bfloat16_rn(w - __bfloat162float(hi));
    *(unsigned short*)(dsm + WS_OFF + k * 144 + c * 2) = __bfloat16_as_ushort(hi);
    *(unsigned short*)(dsm + WS_OFF + 73728 + k * 144 + c * 2) = __bfloat16_as_ushort(lo);
  }

  // ---- state init ----
  const int gtid = bid * NTHR + tid;
  for (int e = gtid; e < 64 * 16 * 256; e += NBLK * NTHR) {
    const int l = e >> 12, rm = e & 4095;
    __stcg(&((float*)g_c)[e], ist[(l * 2 + 0) * 4096 + rm]);
    __stcg(&((float*)g_h)[64 * 16 * 256 + e], ist[(l * 2 + 1) * 4096 + rm]);
  }
  grid_barrier(pbase + 1);

  // thread-invariant ldmatrix bases: krow/m = lane&15, half-sel = lane>>4
  const uint32_t aBase = sb + AS_OFF + wid * 4608 + (lane & 15) * 144 + (lane >> 4) * 16;
  const uint32_t bBase = sb + WS_OFF + (lane & 15) * 144 + (lane >> 4) * 16;
  char* const aW = dsm + AS_OFF + wid * 4608;   // this warp's A slice

  // ---- wavefront ----
  for (int d = 0; d < 127; ++d) {
    const int dlo = (d > 63) ? d - 63 : 0;
    const int dhi = (d < 63) ? d : 63;
    const int ncl = dhi - dlo;
    const int cg = Mb * 8 + wid;

    if (cg <= ncl) {
      const int l = dlo + cg, t = d - l;
      const int pin = t & 1;

      float acc[32];
      #pragma unroll
      for (int i = 0; i < 32; ++i) acc[i] = 0.0f;

      for (int ch = 0; ch < 8; ++ch) {
        __syncwarp();
        // build A chunk: rows br 0..15, k = ch*64 + lane*2 (hi+lo planes)
        const int kg = ch * 64 + lane * 2;
        #pragma unroll
        for (int br = 0; br < 16; ++br) {
          float2 v;
          if (ch < 4) {
            v = (l == 0) ? __ldcg((const float2*)&x[(br * 64 + t) * 256 + kg])
                         : __ldcg((const float2*)&g_h[pin][l - 1][br][kg]);
          } else {
            v = __ldcg((const float2*)&g_h[pin ^ 1][l][br][kg - 256]);
          }
          const __nv_bfloat16 hx = __float2bfloat16_rn(v.x);
          const __nv_bfloat16 hy = __float2bfloat16_rn(v.y);
          const __nv_bfloat16 lx = __float2bfloat16_rn(v.x - __bfloat162float(hx));
          const __nv_bfloat16 ly = __float2bfloat16_rn(v.y - __bfloat162float(hy));
          const uint32_t hw = ((uint32_t)__bfloat16_as_ushort(hy) << 16) | __bfloat16_as_ushort(hx);
          const uint32_t lw = ((uint32_t)__bfloat16_as_ushort(ly) << 16) | __bfloat16_as_ushort(lx);
          *(uint32_t*)(aW + br * 144 + lane * 4) = hw;
          *(uint32_t*)(aW + 2304 + br * 144 + lane * 4) = lw;
        }
        __syncwarp();

        #pragma unroll
        for (int ks = 0; ks < 4; ++ks) {
          uint32_t ah[4], al[4], bh[16], bl[16];
          ldsm4(ah, aBase + ks * 32);
          ldsm4(al, aBase + 2304 + ks * 32);
          const uint32_t bk = bBase + ch * 9216 + ks * 2304;
          #pragma unroll
          for (int np = 0; np < 4; ++np) ldsm4t(&bh[np * 4], bk + np * 32);
          #pragma unroll
          for (int nt = 0; nt < 8; ++nt) mma16816(&acc[nt * 4], ah, bh[nt * 2], bh[nt * 2 + 1]);
          #pragma unroll
          for (int nt = 0; nt < 8; ++nt) mma16816(&acc[nt * 4], al, bh[nt * 2], bh[nt * 2 + 1]);
          #pragma unroll
          for (int np = 0; np < 4; ++np) ldsm4t(&bl[np * 4], bk + 73728 + np * 32);
          #pragma unroll
          for (int nt = 0; nt < 8; ++nt) mma16816(&acc[nt * 4], ah, bl[nt * 2], bl[nt * 2 + 1]);
        }
      }

      // ---- epilogue: thread holds all 4 gates (tile = gate*2 + hcb) ----
      const int r0 = lane >> 2, q = lane & 3;
      #pragma unroll
      for (int hcb = 0; hcb < 2; ++hcb) {
        #pragma unroll
        for (int co = 0; co < 2; ++co) {
          const int hc = hcb * 8 + q * 2 + co;
          const int m = Ns * 16 + hc;
          const float bi = __ldg(&bias[m]);
          const float bj = __ldg(&bias[256 + m]);
          const float bf = __ldg(&bias[512 + m]);
          const float bo = __ldg(&bias[768 + m]);
          #pragma unroll
          for (int rr = 0; rr < 2; ++rr) {
            const int br = r0 + rr * 8;
            const int ai = rr * 2 + co;
            const float zi = acc[(0 + hcb) * 4 + ai] + bi;
            const float zj = acc[(2 + hcb) * 4 + ai] + bj;
            const float zf = acc[(4 + hcb) * 4 + ai] + bf;
            const float zo = acc[(6 + hcb) * 4 + ai] + bo;
            const float lc = __ldcg(&g_c[l][br][m]);
            const float ncv = sigf(zf + 1.0f) * lc + sigf(zi) * tanhfast(zj);
            const float nh = sigf(zo) * tanhfast(ncv);
            __stcg(&g_c[l][br][m], ncv);
            __stcg(&g_h[pin][l][br][m], nh);
            if (l == 63) out[(br * 64 + t) * 256 + m] = nh;
          }
        }
      }
    }
    grid_barrier(pbase + 2 + d);
  }
}

extern "C" void kernel_launch(void* const* d_in, const int* in_sizes, int n_in,
                              void* d_out, int out_size) {
  const float* x    = (const float*)d_in[0];
  const float* ist  = (const float*)d_in[1];
  const float* W    = (const float*)d_in[2];
  const float* bias = (const float*)d_in[3];
  float* out        = (float*)d_out;
  (void)in_sizes; (void)n_in; (void)out_size;
  cudaFuncSetAttribute(lstm_mma, cudaFuncAttributeMaxDynamicSharedMemorySize, DYN_BYTES);
  lstm_mma<<<NBLK, NTHR, DYN_BYTES>>>(x, ist, W, bias, out);
}

// round 6
// speedup vs baseline: 2.4713x; 2.2115x over previous
#include <cuda_runtime.h>
#include <cuda_bf16.h>
#include <cstdint>

// Stacked-LSTM wavefront, mma.sync edition, round 6.
// 128 persistent CTAs x 512 thr. CTA = (Mb, Ns). Warp = (cell wcell = wid>>1,
// N-half nh = wid&1): computes m16 x n32 of cell Mb*8+wcell with split-bf16 x3.
// W resident in SMEM (cols reordered hc*4+gate, 144B rows). A double-buffered
// per cell, built cooperatively by the cell's two warps (named barrier), with
// next-chunk global loads prefetched into regs before current-chunk MMAs.

#define NBLK 128
#define NTHR 512
#define WS_OFF 0                  // hi [512][72]b16 = 73728 ; lo at +73728
#define AS_OFF 147456             // 8 cells x 2 bufs x 4608 B
#define DYN_BYTES 221184

__device__ float g_c[64][16][256];
__device__ float g_h[2][64][16][256];     // parity by t
__device__ unsigned g_count = 0;
__device__ unsigned g_phase = 0;

__device__ __forceinline__ uint32_t smem_u32(const void* p) {
  uint32_t a;
  asm("{ .reg .u64 t; cvta.to.shared.u64 t, %1; cvt.u32.u64 %0, t; }" : "=r"(a) : "l"(p));
  return a;
}
__device__ __forceinline__ void ldsm4(uint32_t* r, uint32_t a) {
  asm volatile("ldmatrix.sync.aligned.m8n8.x4.shared.b16 {%0,%1,%2,%3}, [%4];"
    : "=r"(r[0]), "=r"(r[1]), "=r"(r[2]), "=r"(r[3]) : "r"(a));
}
__device__ __forceinline__ void ldsm4t(uint32_t* r, uint32_t a) {
  asm volatile("ldmatrix.sync.aligned.m8n8.x4.trans.shared.b16 {%0,%1,%2,%3}, [%4];"
    : "=r"(r[0]), "=r"(r[1]), "=r"(r[2]), "=r"(r[3]) : "r"(a));
}
__device__ __forceinline__ void mma16816(float* c, const uint32_t* a, uint32_t b0, uint32_t b1) {
  asm volatile("mma.sync.aligned.m16n8k16.row.col.f32.bf16.bf16.f32 "
    "{%0,%1,%2,%3}, {%4,%5,%6,%7}, {%8,%9}, {%0,%1,%2,%3};"
    : "+f"(c[0]), "+f"(c[1]), "+f"(c[2]), "+f"(c[3])
    : "r"(a[0]), "r"(a[1]), "r"(a[2]), "r"(a[3]), "r"(b0), "r"(b1));
}
#define CELLBAR(id) asm volatile("bar.sync %0, 64;" :: "r"(id) : "memory")

__device__ __forceinline__ float sigf(float v) { return 1.0f / (1.0f + __expf(-v)); }
__device__ __forceinline__ float tanhfast(float v) {
  float e = __expf(2.0f * v);
  return 1.0f - 2.0f / (e + 1.0f);
}

__device__ __forceinline__ void grid_barrier(unsigned target) {
  __syncthreads();
  if (threadIdx.x == 0) {
    __threadfence();
    if (atomicAdd(&g_count, 1) == (unsigned)(NBLK - 1)) {
      atomicExch(&g_count, 0);
      __threadfence();
      atomicAdd(&g_phase, 1);
    } else {
      while (*((volatile unsigned*)&g_phase) != target) { __nanosleep(40); }
    }
    __threadfence();
  }
  __syncthreads();
}

__global__ __launch_bounds__(NTHR, 1) void lstm_mma(
    const float* __restrict__ x,      // (16, 64, 256)
    const float* __restrict__ ist,    // (64, 2, 16, 256)
    const float* __restrict__ W,      // (512, 1024)
    const float* __restrict__ bias,   // (1024,)
    float* __restrict__ out)          // (16, 64, 256)
{
  extern __shared__ __align__(16) char dsm[];
  __shared__ unsigned s_base;

  const int tid = threadIdx.x;
  const int wid = tid >> 5;
  const int lane = tid & 31;
  const int wcell = wid >> 1;       // cell index within CTA (0..7)
  const int nh = wid & 1;           // N-half (0..1)
  const int bid = blockIdx.x;
  const int Ns = bid & 15;
  const int Mb = bid >> 4;
  const uint32_t sb = smem_u32(dsm);

  if (tid == 0) s_base = *((volatile unsigned*)&g_phase);
  __syncthreads();
  const unsigned pbase = s_base;

  // ---- W hi/lo into resident SMEM: col index cc = hc*4 + gate ----
  for (int e = tid; e < 512 * 64; e += NTHR) {
    const int k = e >> 6, cc = e & 63;
    const int hc = cc >> 2, g = cc & 3;
    const float w = W[k * 1024 + g * 256 + Ns * 16 + hc];
    const __nv_bfloat16 hi = __float2bfloat16_rn(w);
    const __nv_bfloat16 lo = __float2bfloat16_rn(w - __bfloat162float(hi));
    *(unsigned short*)(dsm + WS_OFF + k * 144 + cc * 2) = __bfloat16_as_ushort(hi);
    *(unsigned short*)(dsm + WS_OFF + 73728 + k * 144 + cc * 2) = __bfloat16_as_ushort(lo);
  }

  // ---- state init ----
  const int gtid = bid * NTHR + tid;
  for (int e = gtid; e < 64 * 16 * 256; e += NBLK * NTHR) {
    const int l = e >> 12, rm = e & 4095;
    __stcg(&((float*)g_c)[e], ist[(l * 2 + 0) * 4096 + rm]);
    __stcg(&((float*)g_h)[64 * 16 * 256 + e], ist[(l * 2 + 1) * 4096 + rm]);
  }
  grid_barrier(pbase + 1);

  // thread-invariant ldmatrix lane offsets
  const uint32_t loff = (uint32_t)((lane & 15) * 144 + (lane >> 4) * 16);
  const uint32_t aB0 = sb + AS_OFF + wcell * 9216 + loff;     // + (ch&1)*4608
  const uint32_t bB = sb + WS_OFF + loff + nh * 64;           // + ch*9216 + ks*2304
  char* const aS0 = dsm + AS_OFF + wcell * 9216;              // store base

  const int q = lane & 3;
  const int brE = (q & 1) ? (lane >> 2) + 8 : (lane >> 2);    // epilogue row

  // ---- wavefront ----
  for (int d = 0; d < 127; ++d) {
    const int dlo = (d > 63) ? d - 63 : 0;
    const int dhi = (d < 63) ? d : 63;
    const int ncl = dhi - dlo;
    const int cg = Mb * 8 + wcell;

    if (cg <= ncl) {
      const int l = dlo + cg, t = d - l;
      const int pin = t & 1;

      // prefetch c-state for epilogue
      float cpf[4];
      #pragma unroll
      for (int nt = 0; nt < 4; ++nt)
        cpf[nt] = __ldcg(&g_c[l][brE][Ns * 16 + nh * 8 + nt * 2 + (q >> 1)]);

      float acc[16];
      #pragma unroll
      for (int i = 0; i < 16; ++i) acc[i] = 0.0f;

      // prologue: prefetch chunk 0 (rows nh*8..nh*8+7, k pair lane*2)
      float2 pf[8];
      {
        const int kg = lane * 2;
        #pragma unroll
        for (int rr = 0; rr < 8; ++rr) {
          const int br = nh * 8 + rr;
          pf[rr] = (l == 0) ? __ldcg((const float2*)&x[(br * 64 + t) * 256 + kg])
                            : __ldcg((const float2*)&g_h[pin][l - 1][br][kg]);
        }
      }

      for (int ch = 0; ch < 8; ++ch) {
        // store prefetched chunk into buf ch&1 (hi + lo planes)
        char* abuf = aS0 + (ch & 1) * 4608;
        #pragma unroll
        for (int rr = 0; rr < 8; ++rr) {
          const float2 v = pf[rr];
          const __nv_bfloat16 hx = __float2bfloat16_rn(v.x);
          const __nv_bfloat16 hy = __float2bfloat16_rn(v.y);
          const __nv_bfloat16 lx = __float2bfloat16_rn(v.x - __bfloat162float(hx));
          const __nv_bfloat16 ly = __float2bfloat16_rn(v.y - __bfloat162float(hy));
          const int br = nh * 8 + rr;
          *(uint32_t*)(abuf + br * 144 + lane * 4) =
              ((uint32_t)__bfloat16_as_ushort(hy) << 16) | __bfloat16_as_ushort(hx);
          *(uint32_t*)(abuf + 2304 + br * 144 + lane * 4) =
              ((uint32_t)__bfloat16_as_ushort(ly) << 16) | __bfloat16_as_ushort(lx);
        }
        CELLBAR(wcell + 1);

        // prefetch next chunk while MMAing this one
        if (ch < 7) {
          const int chn = ch + 1;
          const int kg = chn * 64 + lane * 2;
          #pragma unroll
          for (int rr = 0; rr < 8; ++rr) {
            const int br = nh * 8 + rr;
            if (chn < 4) {
              pf[rr] = (l == 0) ? __ldcg((const float2*)&x[(br * 64 + t) * 256 + kg])
                                : __ldcg((const float2*)&g_h[pin][l - 1][br][kg]);
            } else {
              pf[rr] = __ldcg((const float2*)&g_h[pin ^ 1][l][br][kg - 256]);
            }
          }
        }

        const uint32_t ab = aB0 + (ch & 1) * 4608;
        #pragma unroll
        for (int ks = 0; ks < 4; ++ks) {
          uint32_t ah[4], al[4], bh[8], bl[8];
          ldsm4(ah, ab + ks * 32);
          ldsm4(al, ab + 2304 + ks * 32);
          const uint32_t bk = bB + ch * 9216 + ks * 2304;
          ldsm4t(&bh[0], bk);
          ldsm4t(&bh[4], bk + 32);
          #pragma unroll
          for (int nt = 0; nt < 4; ++nt) mma16816(&acc[nt * 4], ah, bh[nt * 2], bh[nt * 2 + 1]);
          #pragma unroll
          for (int nt = 0; nt < 4; ++nt) mma16816(&acc[nt * 4], al, bh[nt * 2], bh[nt * 2 + 1]);
          ldsm4t(&bl[0], bk + 73728);
          ldsm4t(&bl[4], bk + 73728 + 32);
          #pragma unroll
          for (int nt = 0; nt < 4; ++nt) mma16816(&acc[nt * 4], ah, bl[nt * 2], bl[nt * 2 + 1]);
        }
      }

      // ---- epilogue: bfly exchange -> each thread has all 4 gates of one (row, hc) ----
      #pragma unroll
      for (int nt = 0; nt < 4; ++nt) {
        const float c0 = acc[nt * 4 + 0], c1 = acc[nt * 4 + 1];
        const float c2 = acc[nt * 4 + 2], c3 = acc[nt * 4 + 3];
        const float e0 = __shfl_xor_sync(0xffffffffu, c0, 1);
        const float e1 = __shfl_xor_sync(0xffffffffu, c1, 1);
        const float e2 = __shfl_xor_sync(0xffffffffu, c2, 1);
        const float e3 = __shfl_xor_sync(0xffffffffu, c3, 1);
        float zi, zj, zf, zo;
        if (!(q & 1)) { zi = c0; zj = c1; zf = e0; zo = e1; }   // even: row r0
        else          { zi = e2; zj = e3; zf = c2; zo = c3; }   // odd:  row r0+8
        const int hc = nh * 8 + nt * 2 + (q >> 1);
        const int m = Ns * 16 + hc;
        zi += __ldg(&bias[m]);
        zj += __ldg(&bias[256 + m]);
        zf += __ldg(&bias[512 + m]);
        zo += __ldg(&bias[768 + m]);
        const float ncv = sigf(zf + 1.0f) * cpf[nt] + sigf(zi) * tanhfast(zj);
        const float nhv = sigf(zo) * tanhfast(ncv);
        __stcg(&g_c[l][brE][m], ncv);
        __stcg(&g_h[pin][l][brE][m], nhv);
        if (l == 63) out[(brE * 64 + t) * 256 + m] = nhv;
      }
    }
    grid_barrier(pbase + 2 + d);
  }
}

extern "C" void kernel_launch(void* const* d_in, const int* in_sizes, int n_in,
                              void* d_out, int out_size) {
  const float* x    = (const float*)d_in[0];
  const float* ist  = (const float*)d_in[1];
  const float* W    = (const float*)d_in[2];
  const float* bias = (const float*)d_in[3];
  float* out        = (float*)d_out;
  (void)in_sizes; (void)n_in; (void)out_size;
  cudaFuncSetAttribute(lstm_mma, cudaFuncAttributeMaxDynamicSharedMemorySize, DYN_BYTES);
  lstm_mma<<<NBLK, NTHR, DYN_BYTES>>>(x, ist, W, bias, out);
}

// round 11
// speedup vs baseline: 3.6310x; 1.4692x over previous
#include <cuda_runtime.h>
#include <cuda_bf16.h>
#include <cstdint>

// Stacked-LSTM, dataflow wavefront (no per-diagonal grid barrier), fix of R7:
// init of g_hb slot 0 now covers all 64 layers (262144 words), not 1/4 of them.
// 128 persistent CTAs x 512 thr. CTA = (lg = bid>>4, Ns = bid&15).
// Warp-pair p (0..7) owns layer l = lg*8+p for all t; warp = (p, nh).
// Sync: cnt[s][l] counts Ns-CTAs that wrote h slot s (s = t+1; s=0 = init).
// h stored packed u32 (bf16 hi | lo<<16) in g_hb, never overwritten.
// W (split bf16 hi/lo, cols hc*4+gate) resident in SMEM. c in registers.

#define NBLK 128
#define NTHR 512
#define WS_OFF 0                  // hi [512][72]b16 ; lo at +73728
#define AS_OFF 147456             // 8 pairs x 2 bufs x 4608 B = 73728
#define DYN_BYTES 221184

__device__ unsigned g_hb[65][64][16][256];   // packed h (s, l, b, col)
__device__ unsigned g_xb[64][16][256];       // packed x (t, b, col)
__device__ int g_cnt[65][64];
__device__ unsigned g_count = 0;
__device__ unsigned g_phase = 0;

__device__ __forceinline__ uint32_t smem_u32(const void* p) {
  uint32_t a;
  asm("{ .reg .u64 t; cvta.to.shared.u64 t, %1; cvt.u32.u64 %0, t; }" : "=r"(a) : "l"(p));
  return a;
}
__device__ __forceinline__ void ldsm4(uint32_t* r, uint32_t a) {
  asm volatile("ldmatrix.sync.aligned.m8n8.x4.shared.b16 {%0,%1,%2,%3}, [%4];"
    : "=r"(r[0]), "=r"(r[1]), "=r"(r[2]), "=r"(r[3]) : "r"(a));
}
__device__ __forceinline__ void ldsm4t(uint32_t* r, uint32_t a) {
  asm volatile("ldmatrix.sync.aligned.m8n8.x4.trans.shared.b16 {%0,%1,%2,%3}, [%4];"
    : "=r"(r[0]), "=r"(r[1]), "=r"(r[2]), "=r"(r[3]) : "r"(a));
}
__device__ __forceinline__ void mma16816(float* c, const uint32_t* a, uint32_t b0, uint32_t b1) {
  asm volatile("mma.sync.aligned.m16n8k16.row.col.f32.bf16.bf16.f32 "
    "{%0,%1,%2,%3}, {%4,%5,%6,%7}, {%8,%9}, {%0,%1,%2,%3};"
    : "+f"(c[0]), "+f"(c[1]), "+f"(c[2]), "+f"(c[3])
    : "r"(a[0]), "r"(a[1]), "r"(a[2]), "r"(a[3]), "r"(b0), "r"(b1));
}
__device__ __forceinline__ int ldcg_i(const int* p) {
  int v; asm volatile("ld.global.cg.s32 %0, [%1];" : "=r"(v) : "l"(p)); return v;
}
#define CELLBAR(id) asm volatile("bar.sync %0, 64;" :: "r"(id) : "memory")

__device__ __forceinline__ float sigf(float v) { return 1.0f / (1.0f + __expf(-v)); }
__device__ __forceinline__ float tanhfast(float v) {
  float e = __expf(2.0f * v);
  return 1.0f - 2.0f / (e + 1.0f);
}
__device__ __forceinline__ unsigned packsplit(float v) {
  const __nv_bfloat16 h = __float2bfloat16_rn(v);
  const __nv_bfloat16 lo = __float2bfloat16_rn(v - __bfloat162float(h));
  return (unsigned)__bfloat16_as_ushort(h) | ((unsigned)__bfloat16_as_ushort(lo) << 16);
}

__device__ __forceinline__ void grid_barrier(unsigned target) {
  __syncthreads();
  if (threadIdx.x == 0) {
    __threadfence();
    if (atomicAdd(&g_count, 1) == (unsigned)(NBLK - 1)) {
      atomicExch(&g_count, 0);
      __threadfence();
      atomicAdd(&g_phase, 1);
    } else {
      while (*((volatile unsigned*)&g_phase) != target) { __nanosleep(40); }
    }
    __threadfence();
  }
  __syncthreads();
}

__global__ __launch_bounds__(NTHR, 1) void lstm_df(
    const float* __restrict__ x,      // (16, 64, 256)
    const float* __restrict__ ist,    // (64, 2, 16, 256)
    const float* __restrict__ W,      // (512, 1024)
    const float* __restrict__ bias,   // (1024,)
    float* __restrict__ out)          // (16, 64, 256)
{
  extern __shared__ __align__(16) char dsm[];
  __shared__ unsigned s_base;

  const int tid = threadIdx.x;
  const int wid = tid >> 5;
  const int lane = tid & 31;
  const int p = wid >> 1;           // pair (0..7)
  const int nh = wid & 1;           // N-half
  const int bid = blockIdx.x;
  const int Ns = bid & 15;
  const int lg = bid >> 4;
  const int l = lg * 8 + p;         // this pair's layer
  const uint32_t sb = smem_u32(dsm);

  if (tid == 0) s_base = *((volatile unsigned*)&g_phase);
  __syncthreads();

  // ---- W hi/lo into resident SMEM: col cc = hc*4 + gate ----
  for (int e = tid; e < 512 * 64; e += NTHR) {
    const int k = e >> 6, cc = e & 63;
    const int hc = cc >> 2, g = cc & 3;
    const float w = W[k * 1024 + g * 256 + Ns * 16 + hc];
    const __nv_bfloat16 hi = __float2bfloat16_rn(w);
    const __nv_bfloat16 lo = __float2bfloat16_rn(w - __bfloat162float(hi));
    *(unsigned short*)(dsm + WS_OFF + k * 144 + cc * 2) = __bfloat16_as_ushort(hi);
    *(unsigned short*)(dsm + WS_OFF + 73728 + k * 144 + cc * 2) = __bfloat16_as_ushort(lo);
  }

  // ---- global init: h slot 0 (ALL 64 layers), packed x, counters ----
  const int gtid = bid * NTHR + tid;
  for (int e = gtid; e < 64 * 16 * 256; e += NBLK * NTHR) {
    const int ll = e >> 12, rm = e & 4095;
    ((unsigned*)g_hb)[e] = packsplit(ist[(ll * 2 + 1) * 4096 + rm]);
  }
  for (int e = gtid; e < 64 * 16 * 256; e += NBLK * NTHR) {
    const int t = e >> 12, b = (e >> 8) & 15, c = e & 255;
    ((unsigned*)g_xb)[e] = packsplit(x[b * 16384 + t * 256 + c]);
  }
  if (gtid < 65 * 64) ((int*)g_cnt)[gtid] = (gtid < 64) ? 16 : 0;
  grid_barrier(s_base + 1);

  // ---- register c-state (this warp's 4 values/thread) ----
  const int q = lane & 3;
  const int brE = (q & 1) ? (lane >> 2) + 8 : (lane >> 2);
  float cst[4];
  #pragma unroll
  for (int nt = 0; nt < 4; ++nt)
    cst[nt] = ist[(l * 2 + 0) * 4096 + brE * 256 + Ns * 16 + nh * 8 + nt * 2 + (q >> 1)];

  // ldmatrix lane offsets (R6 layout)
  const uint32_t loff = (uint32_t)((lane & 15) * 144 + (lane >> 4) * 16);
  const uint32_t aB0 = sb + AS_OFF + p * 9216 + loff;          // + (ch&1)*4608
  const uint32_t bB = sb + WS_OFF + loff + nh * 64;            // + ch*9216 + ks*2304
  char* const aS0 = dsm + AS_OFF + p * 9216;

  // A-build thread map (64 threads per pair)
  const int tid64 = nh * 32 + lane;
  const int arow0 = tid64 >> 4;          // 0..3 (+4i)
  const int ac4 = tid64 & 15;            // uint4 column group

  // ---- t-loop (dataflow) ----
  for (int t = 0; t < 64; ++t) {
    // wait deps: own h(t-1) = slot t ; below h(t) = slot t+1 at layer l-1
    while (ldcg_i(&g_cnt[t][l]) < 16) __nanosleep(30);
    if (l > 0) { while (ldcg_i(&g_cnt[t + 1][l - 1]) < 16) __nanosleep(30); }
    __threadfence();

    float acc[16];
    #pragma unroll
    for (int i = 0; i < 16; ++i) acc[i] = 0.0f;

    // prefetch chunk 0
    const unsigned* slow = (l == 0) ? &g_xb[t][0][0] : &g_hb[t + 1][l - 1][0][0];
    const unsigned* shigh = &g_hb[t][l][0][0];
    uint4 pf[4];
    {
      const unsigned* s0 = slow;      // chunk 0 cols 0..63
      #pragma unroll
      for (int i = 0; i < 4; ++i)
        pf[i] = __ldcg((const uint4*)(s0 + (arow0 + 4 * i) * 256 + ac4 * 4));
    }

    for (int ch = 0; ch < 8; ++ch) {
      // unpack + store chunk into buf ch&1 (hi plane, lo plane)
      char* abuf = aS0 + (ch & 1) * 4608;
      #pragma unroll
      for (int i = 0; i < 4; ++i) {
        const uint4 v = pf[i];
        const unsigned hi01 = __byte_perm(v.x, v.y, 0x5410);
        const unsigned lo01 = __byte_perm(v.x, v.y, 0x7632);
        const unsigned hi23 = __byte_perm(v.z, v.w, 0x5410);
        const unsigned lo23 = __byte_perm(v.z, v.w, 0x7632);
        const int row = arow0 + 4 * i;
        *(uint2*)(abuf + row * 144 + ac4 * 8) = make_uint2(hi01, hi23);
        *(uint2*)(abuf + 2304 + row * 144 + ac4 * 8) = make_uint2(lo01, lo23);
      }
      CELLBAR(p + 1);

      // prefetch next chunk
      if (ch < 7) {
        const int chn = ch + 1;
        const unsigned* s0 = (chn < 4) ? (slow + chn * 64) : (shigh + (chn - 4) * 64);
        #pragma unroll
        for (int i = 0; i < 4; ++i)
          pf[i] = __ldcg((const uint4*)(s0 + (arow0 + 4 * i) * 256 + ac4 * 4));
      }

      const uint32_t ab = aB0 + (ch & 1) * 4608;
      #pragma unroll
      for (int ks = 0; ks < 4; ++ks) {
        uint32_t ah[4], al[4], bh[8], bl[8];
        ldsm4(ah, ab + ks * 32);
        ldsm4(al, ab + 2304 + ks * 32);
        const uint32_t bk = bB + ch * 9216 + ks * 2304;
        ldsm4t(&bh[0], bk);
        ldsm4t(&bh[4], bk + 32);
        #pragma unroll
        for (int nt = 0; nt < 4; ++nt) mma16816(&acc[nt * 4], ah, bh[nt * 2], bh[nt * 2 + 1]);
        #pragma unroll
        for (int nt = 0; nt < 4; ++nt) mma16816(&acc[nt * 4], al, bh[nt * 2], bh[nt * 2 + 1]);
        ldsm4t(&bl[0], bk + 73728);
        ldsm4t(&bl[4], bk + 73728 + 32);
        #pragma unroll
        for (int nt = 0; nt < 4; ++nt) mma16816(&acc[nt * 4], ah, bl[nt * 2], bl[nt * 2 + 1]);
      }
    }

    // ---- epilogue: bfly -> all 4 gates per thread; c in regs ----
    #pragma unroll
    for (int nt = 0; nt < 4; ++nt) {
      const float c0 = acc[nt * 4 + 0], c1 = acc[nt * 4 + 1];
      const float c2 = acc[nt * 4 + 2], c3 = acc[nt * 4 + 3];
      const float e0 = __shfl_xor_sync(0xffffffffu, c0, 1);
      const float e1 = __shfl_xor_sync(0xffffffffu, c1, 1);
      const float e2 = __shfl_xor_sync(0xffffffffu, c2, 1);
      const float e3 = __shfl_xor_sync(0xffffffffu, c3, 1);
      float zi, zj, zf, zo;
      if (!(q & 1)) { zi = c0; zj = c1; zf = e0; zo = e1; }
      else          { zi = e2; zj = e3; zf = c2; zo = c3; }
      const int hc = nh * 8 + nt * 2 + (q >> 1);
      const int m = Ns * 16 + hc;
      zi += __ldg(&bias[m]);
      zj += __ldg(&bias[256 + m]);
      zf += __ldg(&bias[512 + m]);
      zo += __ldg(&bias[768 + m]);
      const float ncv = sigf(zf + 1.0f) * cst[nt] + sigf(zi) * tanhfast(zj);
      const float nhv = sigf(zo) * tanhfast(ncv);
      cst[nt] = ncv;
      __stcg(&g_hb[t + 1][l][brE][m], packsplit(nhv));
      if (l == 63) out[(brE * 64 + t) * 256 + m] = nhv;
    }
    __threadfence();
    CELLBAR(p + 1);
    if (nh == 0 && lane == 0) atomicAdd(&g_cnt[t + 1][l], 1);
  }
}

extern "C" void kernel_launch(void* const* d_in, const int* in_sizes, int n_in,
                              void* d_out, int out_size) {
  const float* x    = (const float*)d_in[0];
  const float* ist  = (const float*)d_in[1];
  const float* W    = (const float*)d_in[2];
  const float* bias = (const float*)d_in[3];
  float* out        = (float*)d_out;
  (void)in_sizes; (void)n_in; (void)out_size;
  cudaFuncSetAttribute(lstm_df, cudaFuncAttributeMaxDynamicSharedMemorySize, DYN_BYTES);
  lstm_df<<<NBLK, NTHR, DYN_BYTES>>>(x, ist, W, bias, out);
}